// round 14
// baseline (speedup 1.0000x reference)
#include <cuda_runtime.h>
#include <cuda_bf16.h>
#include <math.h>

#define BB   128     // batch
#define TT   200     // timesteps
#define CC   40      // codes per visit
#define NCODE 2000
#define DAUX 16
#define EE   128     // embedding dim
#define GG   512     // 4*E
#define HH   256     // mlp hidden
#define THR  384     // lstm threads: 128 producer + 256 recurrence

// packed f32x2 FMA (SASS FFMA2) — only reachable via PTX
#define FMA2(d, a, b, c) \
    asm("fma.rn.f32x2 %0, %1, %2, %3;" : "=l"(d) : "l"(a), "l"(b), "l"(c))

__device__ __forceinline__ float plo(unsigned long long v) {
    return __uint_as_float((unsigned)v);
}
__device__ __forceinline__ float phi(unsigned long long v) {
    return __uint_as_float((unsigned)(v >> 32));
}
__device__ __forceinline__ unsigned long long pack2(float lo, float hi) {
    return (unsigned long long)__float_as_uint(lo) |
           ((unsigned long long)__float_as_uint(hi) << 32);
}

__device__ __forceinline__ unsigned smem_u32(const void* p) {
    unsigned a;
    asm("{ .reg .u64 t; cvta.to.shared.u64 t, %1; cvt.u32.u64 %0, t; }"
        : "=r"(a) : "l"(p));
    return a;
}

// fast, saturation-safe gates (MUFU ex2 + rcp; abs err ~1e-7)
__device__ __forceinline__ float fsig(float x) {
    return __fdividef(1.f, 1.f + __expf(-x));
}
__device__ __forceinline__ float ftanh(float x) {
    return fmaf(2.f, fsig(2.f * x), -1.f);
}

// mbarrier + st.async helpers
__device__ __forceinline__ void mbar_init(unsigned addr, unsigned cnt) {
    asm volatile("mbarrier.init.shared.b64 [%0], %1;" :: "r"(addr), "r"(cnt)
                 : "memory");
}
__device__ __forceinline__ void mbar_arm(unsigned addr, unsigned tx) {
    asm volatile("mbarrier.arrive.expect_tx.shared.b64 _, [%0], %1;"
                 :: "r"(addr), "r"(tx) : "memory");
}
__device__ __forceinline__ void mbar_wait(unsigned addr, unsigned parity) {
    unsigned done;
    asm volatile(
        "{\n\t.reg .pred p;\n\t"
        "mbarrier.try_wait.parity.acquire.cluster.shared::cta.b64 p, [%1], %2;\n\t"
        "selp.b32 %0, 1, 0, p;\n\t}"
        : "=r"(done) : "r"(addr), "r"(parity) : "memory");
    while (!done) {
        asm volatile(
            "{\n\t.reg .pred p;\n\t"
            "mbarrier.try_wait.parity.acquire.cluster.shared::cta.b64 p, [%1], %2, 0x989680;\n\t"
            "selp.b32 %0, 1, 0, p;\n\t}"
            : "=r"(done) : "r"(addr), "r"(parity) : "memory");
    }
}
__device__ __forceinline__ void st_async_f32(unsigned raddr, float v,
                                             unsigned rmbar) {
    asm volatile(
        "st.async.shared::cluster.mbarrier::complete_tx::bytes.f32 [%0], %1, [%2];"
        :: "r"(raddr), "f"(v), "r"(rmbar) : "memory");
}
__device__ __forceinline__ void bar_joint() {
    asm volatile("bar.sync 1, %0;" :: "n"(THR) : "memory");
}

// ---------------- scratch (static device arrays; no runtime allocation) -----
__device__ float g_x   [TT * BB * EE];      // relu(embed), row = t*B + b
__device__ float g_last[BB * EE];           // h at last valid timestep per row

// ---------------- kernel A: multi-hot embed (warp per visit, float4) --------
__global__ void __launch_bounds__(128, 8)
embed_kernel(const int* __restrict__ code,
             const float* __restrict__ aux,
             const float* __restrict__ Wlin,
             const float* __restrict__ blin) {
    int grp = threadIdx.x >> 5, lane = threadIdx.x & 31;
    int bt = blockIdx.x * 4 + grp;          // b*T + t
    int b = bt / TT, t = bt % TT;
    __shared__ int   codes[4][CC];
    __shared__ float flags[4][CC];
    __shared__ float auxs[4][DAUX];
    if (lane < CC)      codes[grp][lane]      = code[bt * CC + lane];
    if (lane + 32 < CC) codes[grp][lane + 32] = code[bt * CC + lane + 32];
    if (lane < DAUX)    auxs[grp][lane]       = aux[bt * DAUX + lane];
    __syncwarp();
    for (int c = lane; c < CC; c += 32) {
        int v = codes[grp][c];
        float f = (v > 0) ? 1.f : 0.f;
        for (int j = 0; j < c; j++)
            if (codes[grp][j] == v) f = 0.f;   // binary multi-hot: dedupe
        flags[grp][c] = f;
    }
    __syncwarp();
    float4 acc = *(const float4*)&blin[lane * 4];
    #pragma unroll 4
    for (int c = 0; c < CC; c++) {
        if (flags[grp][c] != 0.f) {            // uniform across warp
            float4 wv = *(const float4*)&Wlin[(codes[grp][c] - 1) * EE + lane * 4];
            acc.x += wv.x; acc.y += wv.y; acc.z += wv.z; acc.w += wv.w;
        }
    }
    #pragma unroll
    for (int k = 0; k < DAUX; k++) {
        float a = auxs[grp][k];
        float4 wv = *(const float4*)&Wlin[(NCODE + k) * EE + lane * 4];
        acc.x = fmaf(a, wv.x, acc.x); acc.y = fmaf(a, wv.y, acc.y);
        acc.z = fmaf(a, wv.z, acc.z); acc.w = fmaf(a, wv.w, acc.w);
    }
    float4 r;
    r.x = fmaxf(acc.x, 0.f); r.y = fmaxf(acc.y, 0.f);
    r.z = fmaxf(acc.z, 0.f); r.w = fmaxf(acc.w, 0.f);
    *(float4*)&g_x[(t * BB + b) * EE + lane * 4] = r;
}

// ---------------- kernel C: fused warp-specialized cluster LSTM --------------
// 32 clusters x 4 CTAs, 384 threads/CTA. Warps 0-3 (tid<128) = zx producers
// (low wid = low arbiter priority); warps 4-11 (tid>=128) = R10 recurrence
// (high wid = priority). Producers compute zx(t+1)=x(t+1)@Wx+b into a 2-slot
// smem ring during the recurrence's sync windows; one joint bar.sync per step
// hands zx across. Wx in smem [c][k] (conflict-free LDS.128); x LDG-early /
// STS-late double-buffered. h exchange: st.async + tx mbarriers (R10).
#define CLUS 4

struct FS {
    float wx[128][132];      // Wx slice, [tc][k]           (~68 KB)
    float h[2][4][EE];       // double-buffered h            (4 KB)
    float x[2][4][EE];       // x staging, double-buffered   (4 KB)
    float zx[2][4][132];     // zx ring                      (~4.2 KB)
    float z[4][132];         // z staging                    (~2.1 KB)
    unsigned long long mbar[2];
};
#define LSTM_SMEM_BYTES ((int)sizeof(FS))

__global__ void __launch_bounds__(THR, 1) __cluster_dims__(CLUS, 1, 1)
lstm_kernel(const float* __restrict__ Wh, const float* __restrict__ Wx,
            const float* __restrict__ blstm, const int* __restrict__ length) {
    extern __shared__ __align__(16) char smem_raw[];
    FS* S = (FS*)smem_raw;

    int tid = threadIdx.x;                 // 384
    unsigned rank;
    asm("mov.u32 %0, %%cluster_ctarank;" : "=r"(rank));
    int b0 = (blockIdx.x >> 2) * 4;        // 4 batch rows per cluster
    int e0 = rank * 32;

    bool producer = (tid < 128);
    int lane = tid & 31;

    // ---- cooperative prologue: Wx -> smem, h=0, x(0),x(1) staged ------------
    for (int i = tid; i < 128 * 128; i += THR) {
        int k = i >> 7, c = i & 127;
        S->wx[c][k] = Wx[k * GG + ((c >> 5) * EE + e0 + (c & 31))];
    }
    for (int i = tid; i < 2 * 4 * EE; i += THR) (&S->h[0][0][0])[i] = 0.f;
    if (tid < 128) {
        int r = tid >> 5, q = tid & 31;
        *(float4*)&S->x[0][r][q << 2] =
            *(const float4*)&g_x[(0 * BB + b0 + r) * EE + (q << 2)];
        *(float4*)&S->x[1][r][q << 2] =
            *(const float4*)&g_x[(1 * BB + b0 + r) * EE + (q << 2)];
    }
    unsigned mb0 = smem_u32(&S->mbar[0]);
    if (tid == 0) {
        mbar_init(mb0,     1);
        mbar_init(mb0 + 8, 1);
    }
    __syncthreads();
    if (tid == 0) {
        mbar_arm(mb0,     2048);
        mbar_arm(mb0 + 8, 2048);
    }

    // ---- producer identity (tid < 128) --------------------------------------
    int ptc = tid & 127;                   // producer column id 0..127
    float breg = producer ? blstm[(ptc >> 5) * EE + e0 + (ptc & 31)] : 0.f;

    // producers make zx(0) from x slot 0
    if (producer) {
        unsigned long long ax0 = 0ull, ax1 = 0ull, ax2 = 0ull, ax3 = 0ull;
        const float* wxp = S->wx[ptc];
        #pragma unroll
        for (int k4 = 0; k4 < 32; k4++) {
            ulonglong2 wq = *(const ulonglong2*)(wxp + 4 * k4);
            ulonglong2 x0 = *(const ulonglong2*)(&S->x[0][0][4 * k4]);
            ulonglong2 x1 = *(const ulonglong2*)(&S->x[0][1][4 * k4]);
            ulonglong2 x2 = *(const ulonglong2*)(&S->x[0][2][4 * k4]);
            ulonglong2 x3 = *(const ulonglong2*)(&S->x[0][3][4 * k4]);
            FMA2(ax0, x0.x, wq.x, ax0); FMA2(ax0, x0.y, wq.y, ax0);
            FMA2(ax1, x1.x, wq.x, ax1); FMA2(ax1, x1.y, wq.y, ax1);
            FMA2(ax2, x2.x, wq.x, ax2); FMA2(ax2, x2.y, wq.y, ax2);
            FMA2(ax3, x3.x, wq.x, ax3); FMA2(ax3, x3.y, wq.y, ax3);
        }
        S->zx[0][0][ptc] = breg + (plo(ax0) + phi(ax0));
        S->zx[0][1][ptc] = breg + (plo(ax1) + phi(ax1));
        S->zx[0][2][ptc] = breg + (plo(ax2) + phi(ax2));
        S->zx[0][3][ptc] = breg + (plo(ax3) + phi(ax3));
    }
    __syncthreads();

    // ---- recurrence identity (tid >= 128), R10 geometry ---------------------
    int rt = tid - 128;                    // 0..255
    int w8 = rt >> 5;                      // 0..7
    int wr = w8 >> 2, wc = w8 & 3;
    int r0 = 2 * wr, r1 = r0 + 1;
    int gate = lane >> 3, e8 = lane & 7;
    int le = wc * 8 + e8;
    int colg = gate * EE + e0 + le;
    int zc = gate * 32 + le;

    unsigned long long w_reg[64];
    if (!producer) {
        #pragma unroll
        for (int j = 0; j < 64; j++)
            w_reg[j] = pack2(Wh[(2 * j) * GG + colg],
                             Wh[(2 * j + 1) * GG + colg]);
    }

    // epilogue identity: rt < 128 -> slot (row er, e ee)
    bool epi = (!producer) && (rt < 128);
    int er = rt >> 5, ee = rt & 31;
    int Lrow = epi ? length[b0 + er] : 0;
    float cst = 0.f;

    unsigned hbase = smem_u32(&S->h[0][0][0]);
    unsigned peerh[CLUS], peerm[CLUS];
    #pragma unroll
    for (int p = 0; p < CLUS; p++) {
        asm("mapa.shared::cluster.u32 %0, %1, %2;"
            : "=r"(peerh[p]) : "r"(hbase), "r"(p));
        asm("mapa.shared::cluster.u32 %0, %1, %2;"
            : "=r"(peerm[p]) : "r"(mb0), "r"(p));
    }

    // inits + arms + zx(0) visible cluster-wide before any st.async
    asm volatile("barrier.cluster.arrive.aligned;" ::: "memory");
    asm volatile("barrier.cluster.wait.aligned;" ::: "memory");

    int pc0 = 0, pc1 = 0;

    for (int t = 0; t < TT; t++) {
        int buf = t & 1;

        if (producer) {
            // LDG x(t+2) early (latency hidden under production FMA)
            float4 xv;
            bool pf = (t + 2 < TT);
            int r = tid >> 5, q = tid & 31;
            if (pf) xv = *(const float4*)
                &g_x[((t + 2) * BB + b0 + r) * EE + (q << 2)];

            if (t + 1 < TT) {               // produce zx(t+1) from x slot (t+1)&1
                int xs = (t + 1) & 1;
                unsigned long long ax0 = 0ull, ax1 = 0ull, ax2 = 0ull, ax3 = 0ull;
                const float* wxp = S->wx[ptc];
                #pragma unroll
                for (int k4 = 0; k4 < 32; k4++) {
                    ulonglong2 wq = *(const ulonglong2*)(wxp + 4 * k4);
                    ulonglong2 x0 = *(const ulonglong2*)(&S->x[xs][0][4 * k4]);
                    ulonglong2 x1 = *(const ulonglong2*)(&S->x[xs][1][4 * k4]);
                    ulonglong2 x2 = *(const ulonglong2*)(&S->x[xs][2][4 * k4]);
                    ulonglong2 x3 = *(const ulonglong2*)(&S->x[xs][3][4 * k4]);
                    FMA2(ax0, x0.x, wq.x, ax0); FMA2(ax0, x0.y, wq.y, ax0);
                    FMA2(ax1, x1.x, wq.x, ax1); FMA2(ax1, x1.y, wq.y, ax1);
                    FMA2(ax2, x2.x, wq.x, ax2); FMA2(ax2, x2.y, wq.y, ax2);
                    FMA2(ax3, x3.x, wq.x, ax3); FMA2(ax3, x3.y, wq.y, ax3);
                }
                int zs = (t + 1) & 1;
                S->zx[zs][0][ptc] = breg + (plo(ax0) + phi(ax0));
                S->zx[zs][1][ptc] = breg + (plo(ax1) + phi(ax1));
                S->zx[zs][2][ptc] = breg + (plo(ax2) + phi(ax2));
                S->zx[zs][3][ptc] = breg + (plo(ax3) + phi(ax3));
            }
            if (pf)                          // stage x(t+2) into slot t&1
                *(float4*)&S->x[t & 1][r][q << 2] = xv;

            bar_joint();
        } else {
            if (t > 0) {
                unsigned off = (unsigned)buf * 8u;
                unsigned par = buf ? ((unsigned)pc1 & 1u) : ((unsigned)pc0 & 1u);
                mbar_wait(mb0 + off, par);
                if (buf) pc1++; else pc0++;
                if (rt == 0) mbar_arm(mb0 + off, 2048);
            }

            float xw0 = S->zx[buf][r0][zc];
            float xw1 = S->zx[buf][r1][zc];

            unsigned long long a0 = 0ull, a1 = 0ull;
            const float* h0p = S->h[buf][r0];
            const float* h1p = S->h[buf][r1];
            #pragma unroll
            for (int k4 = 0; k4 < 32; k4++) {
                ulonglong2 hv0 = *(const ulonglong2*)(h0p + 4 * k4);
                ulonglong2 hv1 = *(const ulonglong2*)(h1p + 4 * k4);
                FMA2(a0, hv0.x, w_reg[2 * k4],     a0);
                FMA2(a1, hv1.x, w_reg[2 * k4],     a1);
                FMA2(a0, hv0.y, w_reg[2 * k4 + 1], a0);
                FMA2(a1, hv1.y, w_reg[2 * k4 + 1], a1);
            }
            S->z[r0][zc] = xw0 + (plo(a0) + phi(a0));
            S->z[r1][zc] = xw1 + (plo(a1) + phi(a1));

            bar_joint();

            if (epi) {
                float zi = S->z[er][ee];
                float zf = S->z[er][32 + ee];
                float zg = S->z[er][64 + ee];
                float zo = S->z[er][96 + ee];
                cst = fsig(zf) * cst + fsig(zi) * ftanh(zg);
                float h = fsig(zo) * ftanh(cst);

                unsigned hoff = (((unsigned)(buf ^ 1) * 4 + er) * EE
                                 + (e0 + ee)) * 4u;
                unsigned moff = (unsigned)(buf ^ 1) * 8u;
                #pragma unroll
                for (int i = 0; i < CLUS; i++) {
                    int p = ((int)rank + i) & (CLUS - 1);
                    st_async_f32(peerh[p] + hoff, h, peerm[p] + moff);
                }
                if (t + 1 == Lrow) g_last[(b0 + er) * EE + e0 + ee] = h;
            }
        }
    }

    // drain: consumers ensure all peer stores landed; everyone joins cluster bar
    if (!producer) mbar_wait(mb0, (unsigned)pc0 & 1u);
    asm volatile("barrier.cluster.arrive.aligned;" ::: "memory");
    asm volatile("barrier.cluster.wait.aligned;" ::: "memory");
}

// ---------------- kernel D: MLP head + L2-normalize --------------------------
__global__ void __launch_bounds__(256, 1)
head_kernel(const float* __restrict__ W0,
            const float* __restrict__ b0v,
            const float* __restrict__ W1,
            const float* __restrict__ b1v,
            float* __restrict__ out) {
    int b = blockIdx.x;             // 128
    int tid = threadIdx.x;          // 256
    __shared__ float hl[EE];
    __shared__ float m[HH];
    __shared__ float red[HH];
    if (tid < EE) hl[tid] = g_last[b * EE + tid];
    __syncthreads();
    float a0 = b0v[tid], a1 = 0.f, a2 = 0.f, a3 = 0.f;
    #pragma unroll
    for (int k = 0; k < EE; k += 4) {
        a0 = fmaf(hl[k],     W0[(k)     * HH + tid], a0);
        a1 = fmaf(hl[k + 1], W0[(k + 1) * HH + tid], a1);
        a2 = fmaf(hl[k + 2], W0[(k + 2) * HH + tid], a2);
        a3 = fmaf(hl[k + 3], W0[(k + 3) * HH + tid], a3);
    }
    m[tid] = fmaxf((a0 + a1) + (a2 + a3), 0.f);
    __syncthreads();
    float f0 = b1v[tid], f1 = 0.f, f2 = 0.f, f3 = 0.f;
    #pragma unroll
    for (int k = 0; k < HH; k += 4) {
        f0 = fmaf(m[k],     W1[(k)     * HH + tid], f0);
        f1 = fmaf(m[k + 1], W1[(k + 1) * HH + tid], f1);
        f2 = fmaf(m[k + 2], W1[(k + 2) * HH + tid], f2);
        f3 = fmaf(m[k + 3], W1[(k + 3) * HH + tid], f3);
    }
    float f = (f0 + f1) + (f2 + f3);
    red[tid] = f * f;
    __syncthreads();
    for (int s = 128; s > 0; s >>= 1) {
        if (tid < s) red[tid] += red[tid + s];
        __syncthreads();
    }
    out[b * HH + tid] = f / sqrtf(red[0]);
}

// ---------------- launch -----------------------------------------------------
extern "C" void kernel_launch(void* const* d_in, const int* in_sizes, int n_in,
                              void* d_out, int out_size) {
    const int*   code   = (const int*)  d_in[0];
    const float* aux    = (const float*)d_in[1];
    const int*   length = (const int*)  d_in[2];
    // d_in[3] = is_training (unused, inference)
    const float* Wlin   = (const float*)d_in[4];
    const float* blin   = (const float*)d_in[5];
    const float* Wx     = (const float*)d_in[6];
    const float* Wh     = (const float*)d_in[7];
    const float* blstm  = (const float*)d_in[8];
    const float* W0     = (const float*)d_in[9];
    const float* b0v    = (const float*)d_in[10];
    const float* W1     = (const float*)d_in[11];
    const float* b1v    = (const float*)d_in[12];
    float* out = (float*)d_out;

    cudaFuncSetAttribute(lstm_kernel,
                         cudaFuncAttributeMaxDynamicSharedMemorySize,
                         LSTM_SMEM_BYTES);

    embed_kernel<<<BB * TT / 4, 128>>>(code, aux, Wlin, blin);
    lstm_kernel<<<BB, THR, LSTM_SMEM_BYTES>>>(Wh, Wx, blstm, length);
    head_kernel<<<BB, 256>>>(W0, b0v, W1, b1v, out);
}

// round 15
// speedup vs baseline: 1.7137x; 1.7137x over previous
#include <cuda_runtime.h>
#include <cuda_bf16.h>
#include <math.h>

#define BB   128     // batch
#define TT   200     // timesteps
#define CC   40      // codes per visit
#define NCODE 2000
#define DAUX 16
#define EE   128     // embedding dim
#define GG   512     // 4*E
#define HH   256     // mlp hidden

// packed f32x2 FMA (SASS FFMA2) — only reachable via PTX
#define FMA2(d, a, b, c) \
    asm("fma.rn.f32x2 %0, %1, %2, %3;" : "=l"(d) : "l"(a), "l"(b), "l"(c))

__device__ __forceinline__ float plo(unsigned long long v) {
    return __uint_as_float((unsigned)v);
}
__device__ __forceinline__ float phi(unsigned long long v) {
    return __uint_as_float((unsigned)(v >> 32));
}
__device__ __forceinline__ unsigned long long pack2(float lo, float hi) {
    return (unsigned long long)__float_as_uint(lo) |
           ((unsigned long long)__float_as_uint(hi) << 32);
}

__device__ __forceinline__ unsigned smem_u32(const void* p) {
    unsigned a;
    asm("{ .reg .u64 t; cvta.to.shared.u64 t, %1; cvt.u32.u64 %0, t; }"
        : "=r"(a) : "l"(p));
    return a;
}

// fast, saturation-safe gates (MUFU ex2 + rcp; abs err ~1e-7)
__device__ __forceinline__ float fsig(float x) {
    return __fdividef(1.f, 1.f + __expf(-x));
}
__device__ __forceinline__ float ftanh(float x) {
    return fmaf(2.f, fsig(2.f * x), -1.f);
}

// mbarrier + st.async helpers
__device__ __forceinline__ void mbar_init(unsigned addr, unsigned cnt) {
    asm volatile("mbarrier.init.shared.b64 [%0], %1;" :: "r"(addr), "r"(cnt)
                 : "memory");
}
__device__ __forceinline__ void mbar_arm(unsigned addr, unsigned tx) {
    asm volatile("mbarrier.arrive.expect_tx.shared.b64 _, [%0], %1;"
                 :: "r"(addr), "r"(tx) : "memory");
}
__device__ __forceinline__ void mbar_wait(unsigned addr, unsigned parity) {
    unsigned done;
    asm volatile(
        "{\n\t.reg .pred p;\n\t"
        "mbarrier.try_wait.parity.acquire.cluster.shared::cta.b64 p, [%1], %2;\n\t"
        "selp.b32 %0, 1, 0, p;\n\t}"
        : "=r"(done) : "r"(addr), "r"(parity) : "memory");
    while (!done) {
        asm volatile(
            "{\n\t.reg .pred p;\n\t"
            "mbarrier.try_wait.parity.acquire.cluster.shared::cta.b64 p, [%1], %2, 0x989680;\n\t"
            "selp.b32 %0, 1, 0, p;\n\t}"
            : "=r"(done) : "r"(addr), "r"(parity) : "memory");
    }
}
__device__ __forceinline__ void st_async_f32(unsigned raddr, float v,
                                             unsigned rmbar) {
    asm volatile(
        "st.async.shared::cluster.mbarrier::complete_tx::bytes.f32 [%0], %1, [%2];"
        :: "r"(raddr), "f"(v), "r"(rmbar) : "memory");
}

// ---------------- scratch (static device arrays; no runtime allocation) -----
__device__ float g_x   [TT * BB * EE];      // relu(embed), row = t*B + b
__device__ float g_xw  [TT * BB * GG];      // x @ W_x + b_lstm
__device__ float g_last[BB * EE];           // h at last valid timestep per row

// ---------------- kernel A: multi-hot embed (warp per visit, float4) --------
__global__ void __launch_bounds__(128, 8)
embed_kernel(const int* __restrict__ code,
             const float* __restrict__ aux,
             const float* __restrict__ Wlin,
             const float* __restrict__ blin) {
    int grp = threadIdx.x >> 5, lane = threadIdx.x & 31;
    int bt = blockIdx.x * 4 + grp;          // b*T + t
    int b = bt / TT, t = bt % TT;
    __shared__ int   codes[4][CC];
    __shared__ float flags[4][CC];
    __shared__ float auxs[4][DAUX];
    if (lane < CC)      codes[grp][lane]      = code[bt * CC + lane];
    if (lane + 32 < CC) codes[grp][lane + 32] = code[bt * CC + lane + 32];
    if (lane < DAUX)    auxs[grp][lane]       = aux[bt * DAUX + lane];
    __syncwarp();
    for (int c = lane; c < CC; c += 32) {
        int v = codes[grp][c];
        float f = (v > 0) ? 1.f : 0.f;
        for (int j = 0; j < c; j++)
            if (codes[grp][j] == v) f = 0.f;   // binary multi-hot: dedupe
        flags[grp][c] = f;
    }
    __syncwarp();
    float4 acc = *(const float4*)&blin[lane * 4];
    #pragma unroll 4
    for (int c = 0; c < CC; c++) {
        if (flags[grp][c] != 0.f) {            // uniform across warp
            float4 wv = *(const float4*)&Wlin[(codes[grp][c] - 1) * EE + lane * 4];
            acc.x += wv.x; acc.y += wv.y; acc.z += wv.z; acc.w += wv.w;
        }
    }
    #pragma unroll
    for (int k = 0; k < DAUX; k++) {
        float a = auxs[grp][k];
        float4 wv = *(const float4*)&Wlin[(NCODE + k) * EE + lane * 4];
        acc.x = fmaf(a, wv.x, acc.x); acc.y = fmaf(a, wv.y, acc.y);
        acc.z = fmaf(a, wv.z, acc.z); acc.w = fmaf(a, wv.w, acc.w);
    }
    float4 r;
    r.x = fmaxf(acc.x, 0.f); r.y = fmaxf(acc.y, 0.f);
    r.z = fmaxf(acc.z, 0.f); r.w = fmaxf(acc.w, 0.f);
    *(float4*)&g_x[(t * BB + b) * EE + lane * 4] = r;
}

// ---------------- kernel B: xw = x @ W_x + b_lstm  ([25600,128]@[128,512]) --
__global__ void __launch_bounds__(256, 1)
xw_kernel(const float* __restrict__ Wx, const float* __restrict__ blstm) {
    __shared__ float xs[64][68];   // [row][k]
    __shared__ float ws[64][68];   // [col][k]
    int tid = threadIdx.x;
    int row0 = blockIdx.x * 64, col0 = blockIdx.y * 64;
    int ty = tid >> 4, tx = tid & 15;   // rows: ty+16i, cols: tx+16j

    unsigned long long acc[4][4];
    #pragma unroll
    for (int i = 0; i < 4; i++)
        #pragma unroll
        for (int j = 0; j < 4; j++) acc[i][j] = 0ull;

    for (int kb = 0; kb < 128; kb += 64) {
        for (int i = tid; i < 64 * 16; i += 256) {
            int r = i >> 4, kq = i & 15;
            *(float4*)&xs[r][kq << 2] =
                *(const float4*)&g_x[(row0 + r) * EE + kb + (kq << 2)];
        }
        for (int i = tid; i < 64 * 64; i += 256) {
            int k = i >> 6, c = i & 63;
            ws[c][k] = Wx[(kb + k) * GG + col0 + c];
        }
        __syncthreads();
        #pragma unroll
        for (int k = 0; k < 64; k += 4) {
            ulonglong2 av[4], wv[4];
            #pragma unroll
            for (int i = 0; i < 4; i++)
                av[i] = *(const ulonglong2*)&xs[ty + 16 * i][k];
            #pragma unroll
            for (int j = 0; j < 4; j++)
                wv[j] = *(const ulonglong2*)&ws[tx + 16 * j][k];
            #pragma unroll
            for (int i = 0; i < 4; i++)
                #pragma unroll
                for (int j = 0; j < 4; j++) {
                    FMA2(acc[i][j], av[i].x, wv[j].x, acc[i][j]);
                    FMA2(acc[i][j], av[i].y, wv[j].y, acc[i][j]);
                }
        }
        __syncthreads();
    }
    #pragma unroll
    for (int i = 0; i < 4; i++) {
        int r = row0 + ty + 16 * i;
        #pragma unroll
        for (int j = 0; j < 4; j++) {
            int c = col0 + tx + 16 * j;
            g_xw[r * GG + c] = (plo(acc[i][j]) + phi(acc[i][j])) + blstm[c];
        }
    }
}

// ---------------- kernel C: cluster LSTM, CLUS=2, st.async + tx mbarriers ----
// 64 clusters x 2 CTAs, 256 threads/CTA. Cluster owns 2 batch rows; CTA rank
// owns 256 z-cols (4 gates x 64 e, e-slice [64r,64r+64)), 1 col x 2 rows per
// thread (identical FMA issue count to R10). R10 st.async protocol, but
// fan-out per epilogue thread is 2 (self + 1 peer), tx = 1024 B, and the
// sync/skew domain is 2 CTAs instead of 4.
#define CLUS 2

__global__ void __launch_bounds__(256, 1) __cluster_dims__(CLUS, 1, 1)
lstm_kernel(const float* __restrict__ Wh, const int* __restrict__ length) {
    __shared__ __align__(16) float h_sm[2][2][EE];   // double-buffered h (2 rows)
    __shared__ float z_sm[2][292];                   // [row][gate*72 + le]
    __shared__ __align__(8) unsigned long long mbar[2];

    int tid = threadIdx.x;                 // 256
    unsigned rank;
    asm("mov.u32 %0, %%cluster_ctarank;" : "=r"(rank));
    int b0 = (blockIdx.x >> 1) * 2;        // 2 batch rows per cluster
    int e0 = (int)rank * 64;

    int lane = tid & 31, w = tid >> 5;
    int gate = lane >> 3, e8 = lane & 7;
    int le = w * 8 + e8;                   // local e in [0,64)
    int colg = gate * EE + e0 + le;        // z column in [0,512)
    int zc = gate * 72 + le;               // conflict-free: bank = 8*gate + le

    // W_h column -> registers
    unsigned long long w_reg[64];
    #pragma unroll
    for (int j = 0; j < 64; j++)
        w_reg[j] = pack2(Wh[(2 * j) * GG + colg], Wh[(2 * j + 1) * GG + colg]);

    // zero own h buffer 0 (h_0 = 0); init + arm mbarriers
    for (int i = tid; i < 2 * EE; i += 256) (&h_sm[0][0][0])[i] = 0.f;
    unsigned mb0 = smem_u32(&mbar[0]);
    if (tid == 0) {
        mbar_init(mb0,     1);
        mbar_init(mb0 + 8, 1);
    }
    __syncthreads();
    if (tid == 0) {
        mbar_arm(mb0,     1024);           // 2 sources x 128 floats x 4 B
        mbar_arm(mb0 + 8, 1024);
    }

    // epilogue identity (tid < 128): slot = (row er, e e0+ee)
    int er = tid >> 6, ee = tid & 63;      // er in [0,2) for tid<128
    int Lrow = (tid < 128) ? length[b0 + er] : 0;
    float cst = 0.f;

    // peer addresses (h buffers + mbarriers)
    unsigned hbase = smem_u32(&h_sm[0][0][0]);
    unsigned peerh[CLUS], peerm[CLUS];
    #pragma unroll
    for (int p = 0; p < CLUS; p++) {
        asm("mapa.shared::cluster.u32 %0, %1, %2;"
            : "=r"(peerh[p]) : "r"(hbase), "r"(p));
        asm("mapa.shared::cluster.u32 %0, %1, %2;"
            : "=r"(peerm[p]) : "r"(mb0), "r"(p));
    }

    // preload xw for t=0
    float xw0 = g_xw[(b0 + 0) * GG + colg];
    float xw1 = g_xw[(b0 + 1) * GG + colg];

    // inits + arms + h zero visible cluster-wide before any st.async arrives
    asm volatile("barrier.cluster.arrive.aligned;" ::: "memory");
    asm volatile("barrier.cluster.wait.aligned;" ::: "memory");

    int pc0 = 0, pc1 = 0;                  // per-mbarrier use counters

    for (int t = 0; t < TT; t++) {
        int buf = t & 1;

        if (t > 0) {
            unsigned off = (unsigned)buf * 8u;
            unsigned par = buf ? ((unsigned)pc1 & 1u) : ((unsigned)pc0 & 1u);
            mbar_wait(mb0 + off, par);
            if (buf) pc1++; else pc0++;
            if (tid == 0) mbar_arm(mb0 + off, 1024);   // re-arm next phase
        }

        unsigned long long a0 = 0ull, a1 = 0ull;
        const float* h0p = h_sm[buf][0];
        const float* h1p = h_sm[buf][1];
        #pragma unroll
        for (int k4 = 0; k4 < 32; k4++) {
            ulonglong2 hv0 = *(const ulonglong2*)(h0p + 4 * k4);
            ulonglong2 hv1 = *(const ulonglong2*)(h1p + 4 * k4);
            FMA2(a0, hv0.x, w_reg[2 * k4],     a0);
            FMA2(a1, hv1.x, w_reg[2 * k4],     a1);
            FMA2(a0, hv0.y, w_reg[2 * k4 + 1], a0);
            FMA2(a1, hv1.y, w_reg[2 * k4 + 1], a1);
        }
        z_sm[0][zc] = xw0 + (plo(a0) + phi(a0));
        z_sm[1][zc] = xw1 + (plo(a1) + phi(a1));
        __syncthreads();

        if (tid < 128) {
            float zi = z_sm[er][ee];
            float zf = z_sm[er][72 + ee];
            float zg = z_sm[er][144 + ee];
            float zo = z_sm[er][216 + ee];
            cst = fsig(zf) * cst + fsig(zi) * ftanh(zg);
            float h = fsig(zo) * ftanh(cst);

            // publish h_{t+1}: data store carries the completion signal
            unsigned hoff = (((unsigned)(buf ^ 1) * 2 + er) * EE + (e0 + ee)) * 4u;
            unsigned moff = (unsigned)(buf ^ 1) * 8u;
            #pragma unroll
            for (int i = 0; i < CLUS; i++) {
                int p = ((int)rank + i) & (CLUS - 1);
                st_async_f32(peerh[p] + hoff, h, peerm[p] + moff);
            }
            if (t + 1 == Lrow) g_last[(b0 + er) * EE + e0 + ee] = h;
        }

        // prefetch xw for t+1 (latency hidden under wait + next FMA)
        if (t + 1 < TT) {
            xw0 = g_xw[((t + 1) * BB + b0 + 0) * GG + colg];
            xw1 = g_xw[((t + 1) * BB + b0 + 1) * GG + colg];
        }
    }

    // drain: final stores (step 199) target mbar[0]; wait so no CTA exits
    // while the peer's st.async into our smem are in flight
    mbar_wait(mb0, (unsigned)pc0 & 1u);
    asm volatile("barrier.cluster.arrive.aligned;" ::: "memory");
    asm volatile("barrier.cluster.wait.aligned;" ::: "memory");
}

// ---------------- kernel D: MLP head + L2-normalize --------------------------
__global__ void __launch_bounds__(256, 1)
head_kernel(const float* __restrict__ W0,
            const float* __restrict__ b0v,
            const float* __restrict__ W1,
            const float* __restrict__ b1v,
            float* __restrict__ out) {
    int b = blockIdx.x;             // 128
    int tid = threadIdx.x;          // 256
    __shared__ float hl[EE];
    __shared__ float m[HH];
    __shared__ float red[HH];
    if (tid < EE) hl[tid] = g_last[b * EE + tid];
    __syncthreads();
    float a0 = b0v[tid], a1 = 0.f, a2 = 0.f, a3 = 0.f;
    #pragma unroll
    for (int k = 0; k < EE; k += 4) {
        a0 = fmaf(hl[k],     W0[(k)     * HH + tid], a0);
        a1 = fmaf(hl[k + 1], W0[(k + 1) * HH + tid], a1);
        a2 = fmaf(hl[k + 2], W0[(k + 2) * HH + tid], a2);
        a3 = fmaf(hl[k + 3], W0[(k + 3) * HH + tid], a3);
    }
    m[tid] = fmaxf((a0 + a1) + (a2 + a3), 0.f);
    __syncthreads();
    float f0 = b1v[tid], f1 = 0.f, f2 = 0.f, f3 = 0.f;
    #pragma unroll
    for (int k = 0; k < HH; k += 4) {
        f0 = fmaf(m[k],     W1[(k)     * HH + tid], f0);
        f1 = fmaf(m[k + 1], W1[(k + 1) * HH + tid], f1);
        f2 = fmaf(m[k + 2], W1[(k + 2) * HH + tid], f2);
        f3 = fmaf(m[k + 3], W1[(k + 3) * HH + tid], f3);
    }
    float f = (f0 + f1) + (f2 + f3);
    red[tid] = f * f;
    __syncthreads();
    for (int s = 128; s > 0; s >>= 1) {
        if (tid < s) red[tid] += red[tid + s];
        __syncthreads();
    }
    out[b * HH + tid] = f / sqrtf(red[0]);
}

// ---------------- launch -----------------------------------------------------
extern "C" void kernel_launch(void* const* d_in, const int* in_sizes, int n_in,
                              void* d_out, int out_size) {
    const int*   code   = (const int*)  d_in[0];
    const float* aux    = (const float*)d_in[1];
    const int*   length = (const int*)  d_in[2];
    // d_in[3] = is_training (unused, inference)
    const float* Wlin   = (const float*)d_in[4];
    const float* blin   = (const float*)d_in[5];
    const float* Wx     = (const float*)d_in[6];
    const float* Wh     = (const float*)d_in[7];
    const float* blstm  = (const float*)d_in[8];
    const float* W0     = (const float*)d_in[9];
    const float* b0v    = (const float*)d_in[10];
    const float* W1     = (const float*)d_in[11];
    const float* b1v    = (const float*)d_in[12];
    float* out = (float*)d_out;

    embed_kernel<<<BB * TT / 4, 128>>>(code, aux, Wlin, blin);
    dim3 gb(TT * BB / 64, GG / 64);
    xw_kernel<<<gb, 256>>>(Wx, blstm);
    lstm_kernel<<<BB, 256>>>(Wh, length);   // 64 clusters x 2 CTAs
    head_kernel<<<BB, 256>>>(W0, b0v, W1, b1v, out);
}

// round 17
// speedup vs baseline: 1.9151x; 1.1175x over previous
#include <cuda_runtime.h>
#include <cuda_bf16.h>
#include <math.h>

#define BB   128     // batch
#define TT   200     // timesteps
#define CC   40      // codes per visit
#define NCODE 2000
#define DAUX 16
#define EE   128     // embedding dim
#define GG   512     // 4*E
#define HH   256     // mlp hidden

// packed f32x2 FMA (SASS FFMA2) — only reachable via PTX
#define FMA2(d, a, b, c) \
    asm("fma.rn.f32x2 %0, %1, %2, %3;" : "=l"(d) : "l"(a), "l"(b), "l"(c))

__device__ __forceinline__ float plo(unsigned long long v) {
    return __uint_as_float((unsigned)v);
}
__device__ __forceinline__ float phi(unsigned long long v) {
    return __uint_as_float((unsigned)(v >> 32));
}
__device__ __forceinline__ unsigned long long pack2(float lo, float hi) {
    return (unsigned long long)__float_as_uint(lo) |
           ((unsigned long long)__float_as_uint(hi) << 32);
}

__device__ __forceinline__ unsigned smem_u32(const void* p) {
    unsigned a;
    asm("{ .reg .u64 t; cvta.to.shared.u64 t, %1; cvt.u32.u64 %0, t; }"
        : "=r"(a) : "l"(p));
    return a;
}

// fast, saturation-safe gates (MUFU ex2 + rcp; abs err ~1e-7)
__device__ __forceinline__ float fsig(float x) {
    return __fdividef(1.f, 1.f + __expf(-x));
}
__device__ __forceinline__ float ftanh(float x) {
    return fmaf(2.f, fsig(2.f * x), -1.f);
}

// mbarrier + st.async helpers
__device__ __forceinline__ void mbar_init(unsigned addr, unsigned cnt) {
    asm volatile("mbarrier.init.shared.b64 [%0], %1;" :: "r"(addr), "r"(cnt)
                 : "memory");
}
__device__ __forceinline__ void mbar_arm(unsigned addr, unsigned tx) {
    asm volatile("mbarrier.arrive.expect_tx.shared.b64 _, [%0], %1;"
                 :: "r"(addr), "r"(tx) : "memory");
}
__device__ __forceinline__ void mbar_wait(unsigned addr, unsigned parity) {
    unsigned done;
    asm volatile(
        "{\n\t.reg .pred p;\n\t"
        "mbarrier.try_wait.parity.acquire.cluster.shared::cta.b64 p, [%1], %2;\n\t"
        "selp.b32 %0, 1, 0, p;\n\t}"
        : "=r"(done) : "r"(addr), "r"(parity) : "memory");
    while (!done) {
        asm volatile(
            "{\n\t.reg .pred p;\n\t"
            "mbarrier.try_wait.parity.acquire.cluster.shared::cta.b64 p, [%1], %2, 0x989680;\n\t"
            "selp.b32 %0, 1, 0, p;\n\t}"
            : "=r"(done) : "r"(addr), "r"(parity) : "memory");
    }
}
__device__ __forceinline__ void st_async_f32(unsigned raddr, float v,
                                             unsigned rmbar) {
    asm volatile(
        "st.async.shared::cluster.mbarrier::complete_tx::bytes.f32 [%0], %1, [%2];"
        :: "r"(raddr), "f"(v), "r"(rmbar) : "memory");
}

// tf32 helpers
__device__ __forceinline__ unsigned f2tf32(float x) {
    unsigned r;
    asm("cvt.rna.tf32.f32 %0, %1;" : "=r"(r) : "f"(x));
    return r;
}
#define MMA_TF32(d0, d1, d2, d3, a0, a1, a2, a3, b0, b1) \
    asm volatile("mma.sync.aligned.m16n8k8.row.col.f32.tf32.tf32.f32 " \
                 "{%0,%1,%2,%3}, {%4,%5,%6,%7}, {%8,%9}, {%0,%1,%2,%3};" \
                 : "+f"(d0), "+f"(d1), "+f"(d2), "+f"(d3) \
                 : "r"(a0), "r"(a1), "r"(a2), "r"(a3), "r"(b0), "r"(b1))

// ---------------- scratch (static device arrays; no runtime allocation) -----
__device__ float g_x   [TT * BB * EE];      // relu(embed), row = t*B + b
__device__ float g_xw  [TT * BB * GG];      // x @ W_x + b_lstm
__device__ float g_last[BB * EE];           // h at last valid timestep per row

// ---------------- kernel A: multi-hot embed (warp per visit, float4) --------
__global__ void __launch_bounds__(128, 8)
embed_kernel(const int* __restrict__ code,
             const float* __restrict__ aux,
             const float* __restrict__ Wlin,
             const float* __restrict__ blin) {
    int grp = threadIdx.x >> 5, lane = threadIdx.x & 31;
    int bt = blockIdx.x * 4 + grp;          // b*T + t
    int b = bt / TT, t = bt % TT;
    __shared__ int   codes[4][CC];
    __shared__ float flags[4][CC];
    __shared__ float auxs[4][DAUX];
    if (lane < CC)      codes[grp][lane]      = code[bt * CC + lane];
    if (lane + 32 < CC) codes[grp][lane + 32] = code[bt * CC + lane + 32];
    if (lane < DAUX)    auxs[grp][lane]       = aux[bt * DAUX + lane];
    __syncwarp();
    for (int c = lane; c < CC; c += 32) {
        int v = codes[grp][c];
        float f = (v > 0) ? 1.f : 0.f;
        for (int j = 0; j < c; j++)
            if (codes[grp][j] == v) f = 0.f;   // binary multi-hot: dedupe
        flags[grp][c] = f;
    }
    __syncwarp();
    float4 acc = *(const float4*)&blin[lane * 4];
    #pragma unroll 4
    for (int c = 0; c < CC; c++) {
        if (flags[grp][c] != 0.f) {            // uniform across warp
            float4 wv = *(const float4*)&Wlin[(codes[grp][c] - 1) * EE + lane * 4];
            acc.x += wv.x; acc.y += wv.y; acc.z += wv.z; acc.w += wv.w;
        }
    }
    #pragma unroll
    for (int k = 0; k < DAUX; k++) {
        float a = auxs[grp][k];
        float4 wv = *(const float4*)&Wlin[(NCODE + k) * EE + lane * 4];
        acc.x = fmaf(a, wv.x, acc.x); acc.y = fmaf(a, wv.y, acc.y);
        acc.z = fmaf(a, wv.z, acc.z); acc.w = fmaf(a, wv.w, acc.w);
    }
    float4 r;
    r.x = fmaxf(acc.x, 0.f); r.y = fmaxf(acc.y, 0.f);
    r.z = fmaxf(acc.z, 0.f); r.w = fmaxf(acc.w, 0.f);
    *(float4*)&g_x[(t * BB + b) * EE + lane * 4] = r;
}

// ---------------- kernel B: xw = x @ W_x + b via tf32 mma.sync ---------------
// 3-term split precision (hh + hl + lh), error ~3e-6. CTA tile M=64 x N=128,
// K=128. 8 warps (2 M x 4 N), warp tile 32x32 = 2 m16 x 4 n8, 16 k8-steps.
// A smem [row][k] stride 132, B smem [k][n] stride 136 (fragment loads
// bank-conflict-free). hi/lo split in registers at fragment load.
#define AS_STRIDE 132
#define BS_STRIDE 136
#define XW_SMEM ((64 * AS_STRIDE + 128 * BS_STRIDE) * 4)

__global__ void __launch_bounds__(256, 1)
xw_mma_kernel(const float* __restrict__ Wx, const float* __restrict__ blstm) {
    extern __shared__ __align__(16) float sm[];
    float* as = sm;                        // [64][AS_STRIDE]
    float* bs = sm + 64 * AS_STRIDE;       // [128][BS_STRIDE]

    int tid = threadIdx.x;
    int row0 = blockIdx.x * 64, col0 = blockIdx.y * 128;
    int w = tid >> 5, lane = tid & 31;
    int wm = w >> 2, wn = w & 3;           // warp grid 2 x 4
    int gID = lane >> 2, tig = lane & 3;   // mma group / thread-in-group

    // stage A: 64 rows x 128 k (float4, coalesced)
    for (int i = tid; i < 64 * 32; i += 256) {
        int r = i >> 5, kq = i & 31;
        *(float4*)&as[r * AS_STRIDE + kq * 4] =
            *(const float4*)&g_x[(row0 + r) * EE + kq * 4];
    }
    // stage B: 128 k x 128 n (float4, coalesced over n)
    for (int i = tid; i < 128 * 32; i += 256) {
        int k = i >> 5, nq = i & 31;
        *(float4*)&bs[k * BS_STRIDE + nq * 4] =
            *(const float4*)&Wx[k * GG + col0 + nq * 4];
    }
    __syncthreads();

    float acc[2][4][4];
    #pragma unroll
    for (int mt = 0; mt < 2; mt++)
        #pragma unroll
        for (int nt = 0; nt < 4; nt++)
            #pragma unroll
            for (int q = 0; q < 4; q++) acc[mt][nt][q] = 0.f;

    #pragma unroll
    for (int ks = 0; ks < 16; ks++) {
        int k0 = ks * 8;
        // A fragments (hi/lo) for 2 m16 tiles
        unsigned aH[2][4], aL[2][4];
        #pragma unroll
        for (int mt = 0; mt < 2; mt++) {
            int rbase = wm * 32 + mt * 16;
            float v0 = as[(rbase + gID)     * AS_STRIDE + k0 + tig];
            float v1 = as[(rbase + gID + 8) * AS_STRIDE + k0 + tig];
            float v2 = as[(rbase + gID)     * AS_STRIDE + k0 + tig + 4];
            float v3 = as[(rbase + gID + 8) * AS_STRIDE + k0 + tig + 4];
            aH[mt][0] = f2tf32(v0); aL[mt][0] = f2tf32(v0 - __uint_as_float(aH[mt][0]));
            aH[mt][1] = f2tf32(v1); aL[mt][1] = f2tf32(v1 - __uint_as_float(aH[mt][1]));
            aH[mt][2] = f2tf32(v2); aL[mt][2] = f2tf32(v2 - __uint_as_float(aH[mt][2]));
            aH[mt][3] = f2tf32(v3); aL[mt][3] = f2tf32(v3 - __uint_as_float(aH[mt][3]));
        }
        // B fragments (hi/lo) for 4 n8 tiles
        unsigned bH[4][2], bL[4][2];
        #pragma unroll
        for (int nt = 0; nt < 4; nt++) {
            int nbase = wn * 32 + nt * 8;
            float u0 = bs[(k0 + tig)     * BS_STRIDE + nbase + gID];
            float u1 = bs[(k0 + tig + 4) * BS_STRIDE + nbase + gID];
            bH[nt][0] = f2tf32(u0); bL[nt][0] = f2tf32(u0 - __uint_as_float(bH[nt][0]));
            bH[nt][1] = f2tf32(u1); bL[nt][1] = f2tf32(u1 - __uint_as_float(bH[nt][1]));
        }
        #pragma unroll
        for (int mt = 0; mt < 2; mt++)
            #pragma unroll
            for (int nt = 0; nt < 4; nt++) {
                float* d = acc[mt][nt];
                MMA_TF32(d[0], d[1], d[2], d[3],
                         aH[mt][0], aH[mt][1], aH[mt][2], aH[mt][3],
                         bH[nt][0], bH[nt][1]);
                MMA_TF32(d[0], d[1], d[2], d[3],
                         aH[mt][0], aH[mt][1], aH[mt][2], aH[mt][3],
                         bL[nt][0], bL[nt][1]);
                MMA_TF32(d[0], d[1], d[2], d[3],
                         aL[mt][0], aL[mt][1], aL[mt][2], aL[mt][3],
                         bH[nt][0], bH[nt][1]);
            }
    }

    // epilogue: D[r][c] -> g_xw + bias.  d0,d1 @ (gID, 2*tig), d2,d3 @ (gID+8)
    #pragma unroll
    for (int mt = 0; mt < 2; mt++) {
        int rbase = row0 + wm * 32 + mt * 16;
        #pragma unroll
        for (int nt = 0; nt < 4; nt++) {
            int c = col0 + wn * 32 + nt * 8 + 2 * tig;
            float2 bv = *(const float2*)&blstm[c];
            float2 o0, o1;
            o0.x = acc[mt][nt][0] + bv.x; o0.y = acc[mt][nt][1] + bv.y;
            o1.x = acc[mt][nt][2] + bv.x; o1.y = acc[mt][nt][3] + bv.y;
            *(float2*)&g_xw[(rbase + gID)     * GG + c] = o0;
            *(float2*)&g_xw[(rbase + gID + 8) * GG + c] = o1;
        }
    }
}

// ---------------- kernel C: cluster LSTM, CLUS=2, st.async + tx mbarriers ----
#define CLUS 2

__global__ void __launch_bounds__(256, 1) __cluster_dims__(CLUS, 1, 1)
lstm_kernel(const float* __restrict__ Wh, const int* __restrict__ length) {
    __shared__ __align__(16) float h_sm[2][2][EE];   // double-buffered h (2 rows)
    __shared__ float z_sm[2][292];                   // [row][gate*72 + le]
    __shared__ __align__(8) unsigned long long mbar[2];

    int tid = threadIdx.x;                 // 256
    unsigned rank;
    asm("mov.u32 %0, %%cluster_ctarank;" : "=r"(rank));
    int b0 = (blockIdx.x >> 1) * 2;        // 2 batch rows per cluster
    int e0 = (int)rank * 64;

    int lane = tid & 31, w = tid >> 5;
    int gate = lane >> 3, e8 = lane & 7;
    int le = w * 8 + e8;                   // local e in [0,64)
    int colg = gate * EE + e0 + le;        // z column in [0,512)
    int zc = gate * 72 + le;               // conflict-free: bank = 8*gate + le

    // W_h column -> registers
    unsigned long long w_reg[64];
    #pragma unroll
    for (int j = 0; j < 64; j++)
        w_reg[j] = pack2(Wh[(2 * j) * GG + colg], Wh[(2 * j + 1) * GG + colg]);

    // zero own h buffer 0 (h_0 = 0); init + arm mbarriers
    for (int i = tid; i < 2 * EE; i += 256) (&h_sm[0][0][0])[i] = 0.f;
    unsigned mb0 = smem_u32(&mbar[0]);
    if (tid == 0) {
        mbar_init(mb0,     1);
        mbar_init(mb0 + 8, 1);
    }
    __syncthreads();
    if (tid == 0) {
        mbar_arm(mb0,     1024);           // 2 sources x 128 floats x 4 B
        mbar_arm(mb0 + 8, 1024);
    }

    // epilogue identity (tid < 128): slot = (row er, e e0+ee)
    int er = tid >> 6, ee = tid & 63;      // er in [0,2) for tid<128
    int Lrow = (tid < 128) ? length[b0 + er] : 0;
    float cst = 0.f;

    // peer addresses (h buffers + mbarriers)
    unsigned hbase = smem_u32(&h_sm[0][0][0]);
    unsigned peerh[CLUS], peerm[CLUS];
    #pragma unroll
    for (int p = 0; p < CLUS; p++) {
        asm("mapa.shared::cluster.u32 %0, %1, %2;"
            : "=r"(peerh[p]) : "r"(hbase), "r"(p));
        asm("mapa.shared::cluster.u32 %0, %1, %2;"
            : "=r"(peerm[p]) : "r"(mb0), "r"(p));
    }

    // preload xw for t=0
    float xw0 = g_xw[(b0 + 0) * GG + colg];
    float xw1 = g_xw[(b0 + 1) * GG + colg];

    // inits + arms + h zero visible cluster-wide before any st.async arrives
    asm volatile("barrier.cluster.arrive.aligned;" ::: "memory");
    asm volatile("barrier.cluster.wait.aligned;" ::: "memory");

    int pc0 = 0, pc1 = 0;                  // per-mbarrier use counters

    for (int t = 0; t < TT; t++) {
        int buf = t & 1;

        if (t > 0) {
            unsigned off = (unsigned)buf * 8u;
            unsigned par = buf ? ((unsigned)pc1 & 1u) : ((unsigned)pc0 & 1u);
            mbar_wait(mb0 + off, par);
            if (buf) pc1++; else pc0++;
            if (tid == 0) mbar_arm(mb0 + off, 1024);   // re-arm next phase
        }

        unsigned long long a0 = 0ull, a1 = 0ull;
        const float* h0p = h_sm[buf][0];
        const float* h1p = h_sm[buf][1];
        #pragma unroll
        for (int k4 = 0; k4 < 32; k4++) {
            ulonglong2 hv0 = *(const ulonglong2*)(h0p + 4 * k4);
            ulonglong2 hv1 = *(const ulonglong2*)(h1p + 4 * k4);
            FMA2(a0, hv0.x, w_reg[2 * k4],     a0);
            FMA2(a1, hv1.x, w_reg[2 * k4],     a1);
            FMA2(a0, hv0.y, w_reg[2 * k4 + 1], a0);
            FMA2(a1, hv1.y, w_reg[2 * k4 + 1], a1);
        }
        z_sm[0][zc] = xw0 + (plo(a0) + phi(a0));
        z_sm[1][zc] = xw1 + (plo(a1) + phi(a1));
        __syncthreads();

        if (tid < 128) {
            float zi = z_sm[er][ee];
            float zf = z_sm[er][72 + ee];
            float zg = z_sm[er][144 + ee];
            float zo = z_sm[er][216 + ee];
            cst = fsig(zf) * cst + fsig(zi) * ftanh(zg);
            float h = fsig(zo) * ftanh(cst);

            // publish h_{t+1}: data store carries the completion signal
            unsigned hoff = (((unsigned)(buf ^ 1) * 2 + er) * EE + (e0 + ee)) * 4u;
            unsigned moff = (unsigned)(buf ^ 1) * 8u;
            #pragma unroll
            for (int i = 0; i < CLUS; i++) {
                int p = ((int)rank + i) & (CLUS - 1);
                st_async_f32(peerh[p] + hoff, h, peerm[p] + moff);
            }
            if (t + 1 == Lrow) g_last[(b0 + er) * EE + e0 + ee] = h;
        }

        // prefetch xw for t+1 (latency hidden under wait + next FMA)
        if (t + 1 < TT) {
            xw0 = g_xw[((t + 1) * BB + b0 + 0) * GG + colg];
            xw1 = g_xw[((t + 1) * BB + b0 + 1) * GG + colg];
        }
    }

    // drain: final stores (step 199) target mbar[0]; wait so no CTA exits
    // while the peer's st.async into our smem are in flight
    mbar_wait(mb0, (unsigned)pc0 & 1u);
    asm volatile("barrier.cluster.arrive.aligned;" ::: "memory");
    asm volatile("barrier.cluster.wait.aligned;" ::: "memory");
}

// ---------------- kernel D: MLP head + L2-normalize --------------------------
__global__ void __launch_bounds__(256, 1)
head_kernel(const float* __restrict__ W0,
            const float* __restrict__ b0v,
            const float* __restrict__ W1,
            const float* __restrict__ b1v,
            float* __restrict__ out) {
    int b = blockIdx.x;             // 128
    int tid = threadIdx.x;          // 256
    __shared__ float hl[EE];
    __shared__ float m[HH];
    __shared__ float red[HH];
    if (tid < EE) hl[tid] = g_last[b * EE + tid];
    __syncthreads();
    float a0 = b0v[tid], a1 = 0.f, a2 = 0.f, a3 = 0.f;
    #pragma unroll
    for (int k = 0; k < EE; k += 4) {
        a0 = fmaf(hl[k],     W0[(k)     * HH + tid], a0);
        a1 = fmaf(hl[k + 1], W0[(k + 1) * HH + tid], a1);
        a2 = fmaf(hl[k + 2], W0[(k + 2) * HH + tid], a2);
        a3 = fmaf(hl[k + 3], W0[(k + 3) * HH + tid], a3);
    }
    m[tid] = fmaxf((a0 + a1) + (a2 + a3), 0.f);
    __syncthreads();
    float f0 = b1v[tid], f1 = 0.f, f2 = 0.f, f3 = 0.f;
    #pragma unroll
    for (int k = 0; k < HH; k += 4) {
        f0 = fmaf(m[k],     W1[(k)     * HH + tid], f0);
        f1 = fmaf(m[k + 1], W1[(k + 1) * HH + tid], f1);
        f2 = fmaf(m[k + 2], W1[(k + 2) * HH + tid], f2);
        f3 = fmaf(m[k + 3], W1[(k + 3) * HH + tid], f3);
    }
    float f = (f0 + f1) + (f2 + f3);
    red[tid] = f * f;
    __syncthreads();
    for (int s = 128; s > 0; s >>= 1) {
        if (tid < s) red[tid] += red[tid + s];
        __syncthreads();
    }
    out[b * HH + tid] = f / sqrtf(red[0]);
}

// ---------------- launch -----------------------------------------------------
extern "C" void kernel_launch(void* const* d_in, const int* in_sizes, int n_in,
                              void* d_out, int out_size) {
    const int*   code   = (const int*)  d_in[0];
    const float* aux    = (const float*)d_in[1];
    const int*   length = (const int*)  d_in[2];
    // d_in[3] = is_training (unused, inference)
    const float* Wlin   = (const float*)d_in[4];
    const float* blin   = (const float*)d_in[5];
    const float* Wx     = (const float*)d_in[6];
    const float* Wh     = (const float*)d_in[7];
    const float* blstm  = (const float*)d_in[8];
    const float* W0     = (const float*)d_in[9];
    const float* b0v    = (const float*)d_in[10];
    const float* W1     = (const float*)d_in[11];
    const float* b1v    = (const float*)d_in[12];
    float* out = (float*)d_out;

    cudaFuncSetAttribute(xw_mma_kernel,
                         cudaFuncAttributeMaxDynamicSharedMemorySize, XW_SMEM);

    embed_kernel<<<BB * TT / 4, 128>>>(code, aux, Wlin, blin);
    dim3 gx(TT * BB / 64, GG / 128);
    xw_mma_kernel<<<gx, 256, XW_SMEM>>>(Wx, blstm);
    lstm_kernel<<<BB, 256>>>(Wh, length);   // 64 clusters x 2 CTAs
    head_kernel<<<BB, 256>>>(W0, b0v, W1, b1v, out);
}